// round 7
// baseline (speedup 1.0000x reference)
#include <cuda_runtime.h>
#include <cuda_bf16.h>

// XORNet forward: 2-layer LIF spiking net (snntorch Leaky, subtract reset).
// R5: issue-slot bound (fma 49.6 + alu 34.5, issue 77.8, DRAM 25.3).
// This revision repacks state across BATCH LANES (not neurons) so that
// fma.rn.f32x2 (FFMA2, PTX-only) covers the reset subtract AND the layer-2
// dot: ~60 issue slots per warp-timestep vs ~80 in R4.
// Numerics: every packed op is lane-wise IEEE-RN, instruction-for-instruction
// identical rounding chain to R4 (rel_err must stay 8.596e-4):
//   m = ((0.9*m) + cur) - s_prev ; s = (m > 1) ; o = fma-chain(s, w2)

#define SNN_T 20
#define SNN_H 4

union F2 { float2 f; unsigned long long u; };

__device__ __forceinline__ void mul2(F2& d, const F2& a, const F2& b) {
    asm("mul.rn.f32x2 %0, %1, %2;" : "=l"(d.u) : "l"(a.u), "l"(b.u));
}
__device__ __forceinline__ void add2(F2& d, const F2& a, const F2& b) {
    asm("add.rn.f32x2 %0, %1, %2;" : "=l"(d.u) : "l"(a.u), "l"(b.u));
}
// packed fma: d = round(a*b + c), lane-wise IEEE RN (SASS FFMA2)
__device__ __forceinline__ void fma2(F2& d, const F2& a, const F2& b, const F2& c) {
    asm("fma.rn.f32x2 %0, %1, %2, %3;" : "=l"(d.u) : "l"(a.u), "l"(b.u), "l"(c.u));
}
// 1.0f if a > b else 0.0f, single SASS FSET
__device__ __forceinline__ float fset_gt(float a, float b) {
    float r;
    asm("set.gt.f32.f32 %0, %1, %2;" : "=f"(r) : "f"(a), "f"(b));
    return r;
}

__global__ __launch_bounds__(256) void xornet_snn_kernel(
    const float* __restrict__ x,    // [B, 2]
    const float* __restrict__ w1,   // [4, 2]
    const float* __restrict__ w2,   // [1, 4]
    float* __restrict__ out,        // [T, B, 1]
    int B)
{
    const int i = blockIdx.x * blockDim.x + threadIdx.x;  // handles b = 4i..4i+3
    if (i * 4 >= B) return;
    const int Bq = B >> 2;

    // Broadcast weights (L2/L1 hit after first warp).
    float w1r0[SNN_H], w1r1[SNN_H];
    F2 w2b[SNN_H], cn1, c09;
#pragma unroll
    for (int h = 0; h < SNN_H; h++) {
        w1r0[h] = __ldg(&w1[2 * h]);
        w1r1[h] = __ldg(&w1[2 * h + 1]);
        const float w = __ldg(&w2[h]);
        w2b[h].f = make_float2(w, w);
    }
    cn1.f = make_float2(-1.0f, -1.0f);
    c09.f = make_float2(0.9f, 0.9f);

    // x for 4 batch elements: 2x float4.
    const float4 xa = __ldg(&((const float4*)x)[2 * i]);
    const float4 xb = __ldg(&((const float4*)x)[2 * i + 1]);
    const float x0[4] = {xa.x, xa.z, xb.x, xb.z};
    const float x1[4] = {xa.y, xa.w, xb.y, xb.w};

    // cur[h][q]: neuron h, batch lanes (2q, 2q+1). Same k-ascending fma dot.
    F2 cur[SNN_H][2];
#pragma unroll
    for (int h = 0; h < SNN_H; h++)
#pragma unroll
        for (int q = 0; q < 2; q++) {
            cur[h][q].f.x = fmaf(x1[2 * q],     w1r1[h], __fmul_rn(x0[2 * q],     w1r0[h]));
            cur[h][q].f.y = fmaf(x1[2 * q + 1], w1r1[h], __fmul_rn(x0[2 * q + 1], w1r0[h]));
        }

    // State, all packed across batch-lane pairs.
    F2 m1[SNN_H][2], s1[SNN_H][2];  // layer-1 membranes + spikes (1.0/0.0)
    F2 m2[2], s2[2];                // layer-2
#pragma unroll
    for (int h = 0; h < SNN_H; h++)
#pragma unroll
        for (int q = 0; q < 2; q++) { m1[h][q].u = 0ull; s1[h][q].u = 0ull; }
    m2[0].u = 0ull; m2[1].u = 0ull; s2[0].u = 0ull; s2[1].u = 0ull;

    float4* outp = (float4*)out + i;

#pragma unroll
    for (int t = 0; t < SNN_T; t++) {
#pragma unroll
        for (int q = 0; q < 2; q++) {
#pragma unroll
            for (int h = 0; h < SNN_H; h++) {
                F2 mm;
                mul2(mm, m1[h][q], c09);        // 0.9*m        (packed RN)
                add2(mm, mm, cur[h][q]);        // + cur        (packed RN)
                fma2(mm, s1[h][q], cn1, mm);    // - reset      (FFMA2, == sub for s in {0,1})
                m1[h][q] = mm;
                s1[h][q].f.x = fset_gt(mm.f.x, 1.0f);   // spike = (m > 1)
                s1[h][q].f.y = fset_gt(mm.f.y, 1.0f);
            }
            // spk1 @ w2^T for both lanes at once: binary s -> exact products,
            // same k-ascending rounding chain as XLA's fma dot.
            F2 o;
            mul2(o, s1[0][q], w2b[0]);
            fma2(o, s1[1][q], w2b[1], o);
            fma2(o, s1[2][q], w2b[2], o);
            fma2(o, s1[3][q], w2b[3], o);
            // layer-2 LIF, packed
            F2 mm2;
            mul2(mm2, m2[q], c09);
            add2(mm2, mm2, o);
            fma2(mm2, s2[q], cn1, mm2);
            m2[q] = mm2;
            s2[q].f.x = fset_gt(mm2.f.x, 1.0f);
            s2[q].f.y = fset_gt(mm2.f.y, 1.0f);
        }
        float4 ov;
        ov.x = s2[0].f.x; ov.y = s2[0].f.y; ov.z = s2[1].f.x; ov.w = s2[1].f.y;
        *outp = ov;                  // warp-coalesced STG.128
        outp += Bq;
    }
}

extern "C" void kernel_launch(void* const* d_in, const int* in_sizes, int n_in,
                              void* d_out, int out_size)
{
    const float* x  = (const float*)d_in[0];   // [B, 2]
    const float* w1 = (const float*)d_in[1];   // [4, 2]
    const float* w2 = (const float*)d_in[2];   // [1, 4]
    float* out = (float*)d_out;                // [T, B, 1]

    const int B = in_sizes[0] / 2;             // 1,048,576
    const int threads = 256;
    const int nthreads = B / 4;
    const int blocks = (nthreads + threads - 1) / threads;

    xornet_snn_kernel<<<blocks, threads>>>(x, w1, w2, out, B);
}